// round 1
// baseline (speedup 1.0000x reference)
#include <cuda_runtime.h>
#include <cstdint>

// ---------------------------------------------------------------------------
// SpatialWindowSelfAttention: b=2, img 256x256, C=256, 8 heads x 32, 8x8 windows
// Fixed shapes (setup_inputs is deterministic): no padding path needed.
// ---------------------------------------------------------------------------

#define IMG        256
#define BATCH      2
#define CDIM       256
#define NTOK       (BATCH * IMG * IMG)      // 131072
#define HEADS      8
#define HD         32
#define WS         64                        // window tokens (8x8)
#define WIN_SIDE   32                        // windows per image side
#define NWIN       (BATCH * WIN_SIDE * WIN_SIDE) // 2048
#define QKV_DIM    (3 * CDIM)                // 768

// Scratch (device globals: allocation inside kernel_launch is forbidden)
__device__ float g_qkv[(size_t)NTOK * QKV_DIM];   // ~402 MB
__device__ float g_y[(size_t)NTOK * CDIM];        // ~134 MB

// ---------------------------------------------------------------------------
// Generic fp32 GEMM with bias: C[m][n] = sum_k A[m][k] * B[n][k] + bias[n]
// A: [M][K] row-major, B: [N][K] row-major (torch Linear weight layout).
// Tile 128x128, BK=8, 256 threads, 8x8 register tile per thread.
// M % 128 == 0, N % 128 == 0, K % 8 == 0 guaranteed by the call sites.
// ---------------------------------------------------------------------------
__global__ __launch_bounds__(256, 2)
void gemm_bias_kernel(const float* __restrict__ A,
                      const float* __restrict__ Bw,
                      const float* __restrict__ bias,
                      float* __restrict__ C,
                      int M, int N, int K)
{
    __shared__ float As[8][132];   // [k][m], padded stride keeps float4 reads aligned
    __shared__ float Bs[8][132];   // [k][n]

    const int tid = threadIdx.x;
    const int m0 = blockIdx.y * 128;
    const int n0 = blockIdx.x * 128;

    const int ti = tid >> 4;       // 0..15  (row group)
    const int tj = tid & 15;       // 0..15  (col group)

    // Loader mapping: each thread loads one float4 of A and one of B per chunk
    const int lr = tid >> 1;            // 0..127 tile row
    const int lc = (tid & 1) * 4;       // k offset 0 or 4

    const float* Aptr = A + (size_t)(m0 + lr) * K + lc;
    const float* Bptr = Bw + (size_t)(n0 + lr) * K + lc;

    float acc[8][8];
#pragma unroll
    for (int i = 0; i < 8; i++)
#pragma unroll
        for (int j = 0; j < 8; j++) acc[i][j] = 0.f;

    float4 a_next = *(const float4*)Aptr;
    float4 b_next = *(const float4*)Bptr;

    for (int k0 = 0; k0 < K; k0 += 8) {
        // store current chunk (transposed) into smem
        As[lc + 0][lr] = a_next.x;
        As[lc + 1][lr] = a_next.y;
        As[lc + 2][lr] = a_next.z;
        As[lc + 3][lr] = a_next.w;
        Bs[lc + 0][lr] = b_next.x;
        Bs[lc + 1][lr] = b_next.y;
        Bs[lc + 2][lr] = b_next.z;
        Bs[lc + 3][lr] = b_next.w;
        __syncthreads();

        // prefetch next chunk into registers while computing
        if (k0 + 8 < K) {
            a_next = *(const float4*)(Aptr + k0 + 8);
            b_next = *(const float4*)(Bptr + k0 + 8);
        }

#pragma unroll
        for (int kk = 0; kk < 8; kk++) {
            float ar[8], br[8];
            *(float4*)&ar[0] = *(const float4*)&As[kk][ti * 8];
            *(float4*)&ar[4] = *(const float4*)&As[kk][ti * 8 + 4];
            *(float4*)&br[0] = *(const float4*)&Bs[kk][tj * 8];
            *(float4*)&br[4] = *(const float4*)&Bs[kk][tj * 8 + 4];
#pragma unroll
            for (int i = 0; i < 8; i++)
#pragma unroll
                for (int j = 0; j < 8; j++)
                    acc[i][j] += ar[i] * br[j];
        }
        __syncthreads();
    }

    // epilogue: add bias, write 2 float4 per row
    float bias_r[8];
#pragma unroll
    for (int j = 0; j < 8; j++) bias_r[j] = bias[n0 + tj * 8 + j];

#pragma unroll
    for (int i = 0; i < 8; i++) {
        const size_t row = (size_t)(m0 + ti * 8 + i);
        float4 o0, o1;
        o0.x = acc[i][0] + bias_r[0];
        o0.y = acc[i][1] + bias_r[1];
        o0.z = acc[i][2] + bias_r[2];
        o0.w = acc[i][3] + bias_r[3];
        o1.x = acc[i][4] + bias_r[4];
        o1.y = acc[i][5] + bias_r[5];
        o1.z = acc[i][6] + bias_r[6];
        o1.w = acc[i][7] + bias_r[7];
        *(float4*)&C[row * N + n0 + tj * 8]     = o0;
        *(float4*)&C[row * N + n0 + tj * 8 + 4] = o1;
    }
}

// ---------------------------------------------------------------------------
// Window attention: one block per (window, head). 128 threads.
// Reads q/k/v slices from g_qkv, writes y (natural token layout) to g_y.
// ---------------------------------------------------------------------------
__global__ __launch_bounds__(128, 4)
void attn_kernel(const float* __restrict__ qkv,
                 const float* __restrict__ bias_table,
                 float* __restrict__ y)
{
    __shared__ float qs[WS][HD];
    __shared__ float ks[WS][HD];
    __shared__ float vs[WS][HD];
    __shared__ float sc[WS][WS + 1];     // +1 pad: conflict-free softmax rows
    __shared__ float bts[225 * HEADS];   // relative position bias table (7.2 KB)

    const int tid = threadIdx.x;
    const int w   = blockIdx.x;
    const int hh  = blockIdx.y;

    const int bb   = w >> 10;        // window / 1024
    const int widx = w & 1023;
    const int wr   = widx >> 5;
    const int wc   = widx & 31;

    // copy bias table to smem
    for (int i = tid; i < 225 * HEADS; i += 128) bts[i] = bias_table[i];

    // load q, k, v slices for this (window, head): 3 * 64 tokens * 8 float4
    for (int idx = tid; idx < 3 * WS * 8; idx += 128) {
        const int sel = idx >> 9;           // 0=q, 1=k, 2=v
        const int rem = idx & 511;
        const int t   = rem >> 3;           // token in window
        const int c4  = rem & 7;            // float4 within head slice
        const int trow = t >> 3, tcol = t & 7;
        const size_t tok = (size_t)bb * (IMG * IMG)
                         + (size_t)(wr * 8 + trow) * IMG + (wc * 8 + tcol);
        const float4 v4 = *(const float4*)&qkv[tok * QKV_DIM + sel * CDIM + hh * HD + c4 * 4];
        float* dst = (sel == 0) ? &qs[t][c4 * 4] : (sel == 1) ? &ks[t][c4 * 4] : &vs[t][c4 * 4];
        *(float4*)dst = v4;
    }
    __syncthreads();

    // ---- scores: thread handles one q row, half the k range ----
    const int qt  = tid >> 1;
    const int kt0 = (tid & 1) << 5;
    const int qi = qt >> 3, qj = qt & 7;
    const float scale = 0.17677669529663687f;   // 1/sqrt(32)

    float4 q4[8];
#pragma unroll
    for (int dd = 0; dd < 8; dd++) q4[dd] = *(const float4*)&qs[qt][dd * 4];

    for (int kt = kt0; kt < kt0 + 32; kt++) {
        float d = 0.f;
#pragma unroll
        for (int dd = 0; dd < 8; dd++) {
            const float4 k4 = *(const float4*)&ks[kt][dd * 4];
            d += q4[dd].x * k4.x + q4[dd].y * k4.y + q4[dd].z * k4.z + q4[dd].w * k4.w;
        }
        const int ki = kt >> 3, kj = kt & 7;
        const int ridx = (qi - ki + 7) * 15 + (qj - kj + 7);
        sc[qt][kt] = d * scale + bts[ridx * HEADS + hh];
    }
    __syncthreads();

    // ---- softmax: one thread per row (first 64 threads) ----
    if (tid < WS) {
        const int row = tid;
        float m = -1e30f;
#pragma unroll 4
        for (int k = 0; k < WS; k++) m = fmaxf(m, sc[row][k]);
        float s = 0.f;
#pragma unroll 4
        for (int k = 0; k < WS; k++) {
            const float e = __expf(sc[row][k] - m);
            sc[row][k] = e;
            s += e;
        }
        const float inv = 1.f / s;
#pragma unroll 4
        for (int k = 0; k < WS; k++) sc[row][k] *= inv;
    }
    __syncthreads();

    // ---- y = att @ v: thread handles (q row, 16 channels) ----
    const int d0 = (tid & 1) * 16;
    float4 a0 = {0,0,0,0}, a1 = {0,0,0,0}, a2 = {0,0,0,0}, a3 = {0,0,0,0};
    for (int kt = 0; kt < WS; kt++) {
        const float wgt = sc[qt][kt];
        const float4 v0 = *(const float4*)&vs[kt][d0];
        const float4 v1 = *(const float4*)&vs[kt][d0 + 4];
        const float4 v2 = *(const float4*)&vs[kt][d0 + 8];
        const float4 v3 = *(const float4*)&vs[kt][d0 + 12];
        a0.x += wgt * v0.x; a0.y += wgt * v0.y; a0.z += wgt * v0.z; a0.w += wgt * v0.w;
        a1.x += wgt * v1.x; a1.y += wgt * v1.y; a1.z += wgt * v1.z; a1.w += wgt * v1.w;
        a2.x += wgt * v2.x; a2.y += wgt * v2.y; a2.z += wgt * v2.z; a2.w += wgt * v2.w;
        a3.x += wgt * v3.x; a3.y += wgt * v3.y; a3.z += wgt * v3.z; a3.w += wgt * v3.w;
    }

    {
        const int trow = qt >> 3, tcol = qt & 7;
        const size_t tok = (size_t)bb * (IMG * IMG)
                         + (size_t)(wr * 8 + trow) * IMG + (wc * 8 + tcol);
        float* dst = &y[tok * CDIM + hh * HD + d0];
        *(float4*)&dst[0]  = a0;
        *(float4*)&dst[4]  = a1;
        *(float4*)&dst[8]  = a2;
        *(float4*)&dst[12] = a3;
    }
}

// ---------------------------------------------------------------------------
// Inputs (metadata order): 0=x, 1=h, 2=w, 3=wqkv_w, 4=wqkv_b, 5=wp_w, 6=wp_b,
// 7=bias_table. Output: float32 [2, 65536, 256].
// ---------------------------------------------------------------------------
extern "C" void kernel_launch(void* const* d_in, const int* in_sizes, int n_in,
                              void* d_out, int out_size)
{
    (void)in_sizes; (void)n_in; (void)out_size;
    const float* x          = (const float*)d_in[0];
    const float* wqkv_w     = (const float*)d_in[3];
    const float* wqkv_b     = (const float*)d_in[4];
    const float* wp_w       = (const float*)d_in[5];
    const float* wp_b       = (const float*)d_in[6];
    const float* bias_table = (const float*)d_in[7];
    float* out = (float*)d_out;

    float *qkv_ptr, *y_ptr;
    cudaGetSymbolAddress((void**)&qkv_ptr, g_qkv);
    cudaGetSymbolAddress((void**)&y_ptr, g_y);

    // 1) QKV projection: [131072 x 256] x [768 x 256]^T + b
    gemm_bias_kernel<<<dim3(QKV_DIM / 128, NTOK / 128), 256>>>(
        x, wqkv_w, wqkv_b, qkv_ptr, NTOK, QKV_DIM, CDIM);

    // 2) windowed attention per (window, head)
    attn_kernel<<<dim3(NWIN, HEADS), 128>>>(qkv_ptr, bias_table, y_ptr);

    // 3) output projection: [131072 x 256] x [256 x 256]^T + b
    gemm_bias_kernel<<<dim3(CDIM / 128, NTOK / 128), 256>>>(
        y_ptr, wp_w, wp_b, out, NTOK, CDIM, CDIM);
}

// round 3
// speedup vs baseline: 2.2739x; 2.2739x over previous
#include <cuda_runtime.h>
#include <cstdint>

// ---------------------------------------------------------------------------
// SpatialWindowSelfAttention: b=2, img 256x256, C=256, 8 heads x 32, 8x8 windows
// GEMMs via mma.sync tf32 (portable, no 'a'-target PTX). Attention fp32 SIMT,
// register-tiled.
// ---------------------------------------------------------------------------

#define IMG        256
#define BATCH      2
#define CDIM       256
#define NTOK       (BATCH * IMG * IMG)      // 131072
#define HEADS      8
#define HD         32
#define WS         64
#define NWIN       2048
#define QKV_DIM    (3 * CDIM)               // 768
#define GK         256

#define BK   16
#define AP   20                             // smem row pitch (words): 16 data + 4 pad

// Scratch (no allocation allowed in kernel_launch)
__device__ float g_qkv[(size_t)NTOK * QKV_DIM];
__device__ float g_y[(size_t)NTOK * CDIM];

__device__ __forceinline__ uint32_t smem_u32(const void* p) {
    uint32_t a;
    asm("{ .reg .u64 t; cvta.to.shared.u64 t, %1; cvt.u32.u64 %0, t; }" : "=r"(a) : "l"(p));
    return a;
}
__device__ __forceinline__ void cp16(uint32_t s, const void* g) {
    asm volatile("cp.async.cg.shared.global [%0], [%1], 16;\n" :: "r"(s), "l"(g) : "memory");
}
#define CP_COMMIT() asm volatile("cp.async.commit_group;\n" ::: "memory")
template <int N>
__device__ __forceinline__ void cp_wait() {
    asm volatile("cp.async.wait_group %0;\n" :: "n"(N) : "memory");
}

__device__ __forceinline__ void mma_tf32(float* d, const uint32_t* a, const uint32_t* b) {
    asm volatile(
        "mma.sync.aligned.m16n8k8.row.col.f32.tf32.tf32.f32 "
        "{%0,%1,%2,%3},{%4,%5,%6,%7},{%8,%9},{%0,%1,%2,%3};"
        : "+f"(d[0]), "+f"(d[1]), "+f"(d[2]), "+f"(d[3])
        : "r"(a[0]), "r"(a[1]), "r"(a[2]), "r"(a[3]), "r"(b[0]), "r"(b[1]));
}

// ---------------------------------------------------------------------------
// tf32 tensor-core GEMM: C[m][n] = sum_k A[m][k]*B[n][k] + bias[n]
// A:[M][256], B:[N][256] row-major. grid=(N/128, M/128), 256 threads.
// 8 warps as 2(m) x 4(n): warp tile 64x32. BK=16, double-buffered cp.async.
// ---------------------------------------------------------------------------
__global__ void __launch_bounds__(256, 2)
gemm_mma_kernel(const float* __restrict__ A,
                const float* __restrict__ Bw,
                const float* __restrict__ bias,
                float* __restrict__ C, int N)
{
    __shared__ float As[2][128 * AP];
    __shared__ float Bs[2][128 * AP];

    const int tid  = threadIdx.x;
    const int lane = tid & 31;
    const int wid  = tid >> 5;
    const int g    = lane >> 2;
    const int tig  = lane & 3;
    const int wm   = (wid & 1) * 64;
    const int wn   = (wid >> 1) * 32;
    const int m0   = blockIdx.y * 128;
    const int n0   = blockIdx.x * 128;

    const uint32_t sA = smem_u32(&As[0][0]);
    const uint32_t sB = smem_u32(&Bs[0][0]);
    const float* Ag = A  + (size_t)m0 * GK;
    const float* Bg = Bw + (size_t)n0 * GK;

    float acc[4][4][4];
#pragma unroll
    for (int i = 0; i < 4; i++)
#pragma unroll
        for (int j = 0; j < 4; j++)
#pragma unroll
            for (int c = 0; c < 4; c++) acc[i][j][c] = 0.f;

    // loader: 512 16B chunks per operand per stage; 2 A + 2 B per thread
    const int r0c = tid >> 2, p0 = (tid & 3) * 4;
    const int r1c = (tid + 256) >> 2, p1 = ((tid + 256) & 3) * 4;

    auto load_stage = [&](int it, int s) {
        const int k0 = it * BK;
        const uint32_t so = (uint32_t)s * 128 * AP * 4;
        cp16(sA + so + (r0c * AP + p0) * 4, Ag + (size_t)r0c * GK + k0 + p0);
        cp16(sA + so + (r1c * AP + p1) * 4, Ag + (size_t)r1c * GK + k0 + p1);
        cp16(sB + so + (r0c * AP + p0) * 4, Bg + (size_t)r0c * GK + k0 + p0);
        cp16(sB + so + (r1c * AP + p1) * 4, Bg + (size_t)r1c * GK + k0 + p1);
        CP_COMMIT();
    };

    load_stage(0, 0);

#pragma unroll 1
    for (int it = 0; it < GK / BK; it++) {
        if (it + 1 < GK / BK) {
            load_stage(it + 1, (it + 1) & 1);
            cp_wait<1>();
        } else {
            cp_wait<0>();
        }
        __syncthreads();

        const int s = it & 1;
#pragma unroll
        for (int kk = 0; kk < BK; kk += 8) {
            uint32_t a[4][4], b[4][2];
#pragma unroll
            for (int mf = 0; mf < 4; mf++) {
                const int r = wm + mf * 16 + g;
                a[mf][0] = __float_as_uint(As[s][r * AP + kk + tig]);
                a[mf][1] = __float_as_uint(As[s][(r + 8) * AP + kk + tig]);
                a[mf][2] = __float_as_uint(As[s][r * AP + kk + tig + 4]);
                a[mf][3] = __float_as_uint(As[s][(r + 8) * AP + kk + tig + 4]);
            }
#pragma unroll
            for (int nf = 0; nf < 4; nf++) {
                const int q = wn + nf * 8 + g;
                b[nf][0] = __float_as_uint(Bs[s][q * AP + kk + tig]);
                b[nf][1] = __float_as_uint(Bs[s][q * AP + kk + tig + 4]);
            }
#pragma unroll
            for (int mf = 0; mf < 4; mf++)
#pragma unroll
                for (int nf = 0; nf < 4; nf++)
                    mma_tf32(acc[mf][nf], a[mf], b[nf]);
        }
        __syncthreads();
    }

    // epilogue
#pragma unroll
    for (int mf = 0; mf < 4; mf++) {
        const int r0 = m0 + wm + mf * 16 + g;
        const int r1 = r0 + 8;
#pragma unroll
        for (int nf = 0; nf < 4; nf++) {
            const int col = n0 + wn + nf * 8 + 2 * tig;
            const float2 bv = *(const float2*)&bias[col];
            float2 o0, o1;
            o0.x = acc[mf][nf][0] + bv.x;
            o0.y = acc[mf][nf][1] + bv.y;
            o1.x = acc[mf][nf][2] + bv.x;
            o1.y = acc[mf][nf][3] + bv.y;
            *(float2*)&C[(size_t)r0 * N + col] = o0;
            *(float2*)&C[(size_t)r1 * N + col] = o1;
        }
    }
}

// ---------------------------------------------------------------------------
// Window attention: one block per (window, head). 128 threads, register-tiled.
// ---------------------------------------------------------------------------
__global__ __launch_bounds__(128, 4)
void attn_kernel(const float* __restrict__ qkv,
                 const float* __restrict__ bias_table,
                 float* __restrict__ y)
{
    __shared__ float qs[WS][36];          // pitch 36: halves q-load conflicts
    __shared__ float ks[WS][32];          // column slot swizzled by (t>>3)&7
    __shared__ float vs[WS][32];
    __shared__ float sc[WS][76];          // pitch 76: conflict-free trow reads
    __shared__ float bt[225];             // per-head bias slice

    const int tid = threadIdx.x;
    const int w   = blockIdx.x;
    const int hh  = blockIdx.y;
    const int bb   = w >> 10;
    const int widx = w & 1023;
    const int wr   = widx >> 5;
    const int wc   = widx & 31;

    for (int i = tid; i < 225; i += 128) bt[i] = bias_table[i * HEADS + hh];

    // load q,k,v head slices: 3 * 64 tokens * 8 float4
    for (int idx = tid; idx < 3 * WS * 8; idx += 128) {
        const int sel = idx >> 9;
        const int rem = idx & 511;
        const int t   = rem >> 3;
        const int c4  = rem & 7;
        const int trw = t >> 3, tcl = t & 7;
        const size_t tok = (size_t)bb * (IMG * IMG)
                         + (size_t)(wr * 8 + trw) * IMG + (wc * 8 + tcl);
        const float4 v4 = *(const float4*)&qkv[tok * QKV_DIM + sel * CDIM + hh * HD + c4 * 4];
        if (sel == 0)      *(float4*)&qs[t][c4 * 4] = v4;
        else if (sel == 1) *(float4*)&ks[t][(c4 ^ (t >> 3)) * 4] = v4;   // swizzle
        else               *(float4*)&vs[t][c4 * 4] = v4;
    }
    __syncthreads();

    const int trow = tid >> 3;        // 0..15
    const int tcol = tid & 7;         // 0..7
    const int qb = trow * 4;
    const int kb = tcol * 8;
    const float scale = 0.17677669529663687f;

    // ---- scores: 4q x 8k per thread ----
    {
        float s[4][8];
#pragma unroll
        for (int i = 0; i < 4; i++)
#pragma unroll
            for (int j = 0; j < 8; j++) s[i][j] = 0.f;

#pragma unroll
        for (int d4 = 0; d4 < 8; d4++) {
            float4 q4[4], k4[8];
#pragma unroll
            for (int i = 0; i < 4; i++) q4[i] = *(const float4*)&qs[qb + i][d4 * 4];
#pragma unroll
            for (int j = 0; j < 8; j++) k4[j] = *(const float4*)&ks[kb + j][(d4 ^ tcol) * 4];
#pragma unroll
            for (int i = 0; i < 4; i++)
#pragma unroll
                for (int j = 0; j < 8; j++)
                    s[i][j] += q4[i].x * k4[j].x + q4[i].y * k4[j].y
                             + q4[i].z * k4[j].z + q4[i].w * k4[j].w;
        }

#pragma unroll
        for (int i = 0; i < 4; i++) {
            const int qt = qb + i;
            const int qi = qt >> 3, qj = qt & 7;
            float4 o[2];
#pragma unroll
            for (int j = 0; j < 8; j++) {
                const int kt = kb + j;
                const int ki = kt >> 3, kj = kt & 7;
                ((float*)o)[j] = s[i][j] * scale + bt[(qi - ki + 7) * 15 + (qj - kj + 7)];
            }
            *(float4*)&sc[qt][kb]     = o[0];
            *(float4*)&sc[qt][kb + 4] = o[1];
        }
    }
    __syncthreads();

    // ---- softmax: 2 threads per row, shfl combine ----
    {
        const int row  = tid >> 1;
        const int half = tid & 1;
        float* sr = &sc[row][half * 32];
        float m = -1e30f;
#pragma unroll 8
        for (int k = 0; k < 32; k++) m = fmaxf(m, sr[k]);
        const float mo = __shfl_xor_sync(0xffffffffu, m, 1);
        const float M = fmaxf(m, mo);
        float ssum = 0.f;
#pragma unroll 8
        for (int k = 0; k < 32; k++) {
            const float e = __expf(sr[k] - M);
            sr[k] = e;
            ssum += e;
        }
        const float so = __shfl_xor_sync(0xffffffffu, ssum, 1);
        const float inv = 1.f / (ssum + so);
#pragma unroll 8
        for (int k = 0; k < 32; k++) sr[k] *= inv;
    }
    __syncthreads();

    // ---- y = att @ v: 4q x 4d per thread ----
    {
        const int db = tcol * 4;
        float a[4][4];
#pragma unroll
        for (int i = 0; i < 4; i++)
#pragma unroll
            for (int c = 0; c < 4; c++) a[i][c] = 0.f;

#pragma unroll
        for (int kt = 0; kt < WS; kt += 4) {
            float4 w4[4], v4[4];
#pragma unroll
            for (int i = 0; i < 4; i++) w4[i] = *(const float4*)&sc[qb + i][kt];
#pragma unroll
            for (int j = 0; j < 4; j++) v4[j] = *(const float4*)&vs[kt + j][db];
#pragma unroll
            for (int i = 0; i < 4; i++) {
                a[i][0] += w4[i].x * v4[0].x + w4[i].y * v4[1].x + w4[i].z * v4[2].x + w4[i].w * v4[3].x;
                a[i][1] += w4[i].x * v4[0].y + w4[i].y * v4[1].y + w4[i].z * v4[2].y + w4[i].w * v4[3].y;
                a[i][2] += w4[i].x * v4[0].z + w4[i].y * v4[1].z + w4[i].z * v4[2].z + w4[i].w * v4[3].z;
                a[i][3] += w4[i].x * v4[0].w + w4[i].y * v4[1].w + w4[i].z * v4[2].w + w4[i].w * v4[3].w;
            }
        }

#pragma unroll
        for (int i = 0; i < 4; i++) {
            const int qt = qb + i;
            const int trw = qt >> 3, tcl = qt & 7;
            const size_t tok = (size_t)bb * (IMG * IMG)
                             + (size_t)(wr * 8 + trw) * IMG + (wc * 8 + tcl);
            float4 o;
            o.x = a[i][0]; o.y = a[i][1]; o.z = a[i][2]; o.w = a[i][3];
            *(float4*)&y[tok * CDIM + hh * HD + db] = o;
        }
    }
}

// ---------------------------------------------------------------------------
extern "C" void kernel_launch(void* const* d_in, const int* in_sizes, int n_in,
                              void* d_out, int out_size)
{
    (void)in_sizes; (void)n_in; (void)out_size;
    const float* x          = (const float*)d_in[0];
    const float* wqkv_w     = (const float*)d_in[3];
    const float* wqkv_b     = (const float*)d_in[4];
    const float* wp_w       = (const float*)d_in[5];
    const float* wp_b       = (const float*)d_in[6];
    const float* bias_table = (const float*)d_in[7];
    float* out = (float*)d_out;

    float *qkv_ptr, *y_ptr;
    cudaGetSymbolAddress((void**)&qkv_ptr, g_qkv);
    cudaGetSymbolAddress((void**)&y_ptr, g_y);

    // 1) QKV projection: [131072 x 256] x [768 x 256]^T + b
    gemm_mma_kernel<<<dim3(QKV_DIM / 128, NTOK / 128), 256>>>(
        x, wqkv_w, wqkv_b, qkv_ptr, QKV_DIM);

    // 2) windowed attention per (window, head)
    attn_kernel<<<dim3(NWIN, HEADS), 128>>>(qkv_ptr, bias_table, y_ptr);

    // 3) output projection: [131072 x 256] x [256 x 256]^T + b
    gemm_mma_kernel<<<dim3(CDIM / 128, NTOK / 128), 256>>>(
        y_ptr, wp_w, wp_b, out, CDIM);
}

// round 4
// speedup vs baseline: 3.0823x; 1.3555x over previous
#include <cuda_runtime.h>
#include <cstdint>

// ---------------------------------------------------------------------------
// SpatialWindowSelfAttention: b=2, img 256x256, C=256, 8 heads x 32, 8x8 windows
// All matmuls on tensor cores (mma.sync tf32 + ldmatrix), RN-rounded inputs.
// ---------------------------------------------------------------------------

#define IMG        256
#define BATCH      2
#define CDIM       256
#define NTOK       (BATCH * IMG * IMG)      // 131072
#define HEADS      8
#define HD         32
#define WS         64
#define NWIN       2048
#define QKV_DIM    (3 * CDIM)               // 768
#define GK         256

// Scratch (device globals: no allocation allowed in kernel_launch)
__device__ float g_x  [(size_t)NTOK * CDIM];     // tf32-rounded x
__device__ float g_wq [(size_t)QKV_DIM * CDIM];  // tf32-rounded wqkv
__device__ float g_wp [(size_t)CDIM * CDIM];     // tf32-rounded wp
__device__ float g_qkv[(size_t)NTOK * QKV_DIM];
__device__ float g_y  [(size_t)NTOK * CDIM];

// ---------------------------------------------------------------------------
// helpers
// ---------------------------------------------------------------------------
__device__ __forceinline__ uint32_t smem_u32(const void* p) {
    uint32_t a;
    asm("{ .reg .u64 t; cvta.to.shared.u64 t, %1; cvt.u32.u64 %0, t; }" : "=r"(a) : "l"(p));
    return a;
}
__device__ __forceinline__ float tf32_rn(float x) {
    uint32_t u;
    asm("cvt.rna.tf32.f32 %0, %1;" : "=r"(u) : "f"(x));
    return __uint_as_float(u);
}
__device__ __forceinline__ void cp16(uint32_t s, const void* g) {
    asm volatile("cp.async.cg.shared.global [%0], [%1], 16;\n" :: "r"(s), "l"(g) : "memory");
}
#define CP_COMMIT() asm volatile("cp.async.commit_group;\n" ::: "memory")
template <int N>
__device__ __forceinline__ void cp_wait() {
    asm volatile("cp.async.wait_group %0;\n" :: "n"(N) : "memory");
}
__device__ __forceinline__ void ldsm4(uint32_t& r0, uint32_t& r1, uint32_t& r2,
                                      uint32_t& r3, uint32_t addr) {
    asm volatile("ldmatrix.sync.aligned.m8n8.x4.shared.b16 {%0,%1,%2,%3}, [%4];"
                 : "=r"(r0), "=r"(r1), "=r"(r2), "=r"(r3) : "r"(addr));
}
__device__ __forceinline__ void mma_tf32(float* d, const uint32_t* a, const uint32_t* b) {
    asm volatile(
        "mma.sync.aligned.m16n8k8.row.col.f32.tf32.tf32.f32 "
        "{%0,%1,%2,%3},{%4,%5,%6,%7},{%8,%9},{%0,%1,%2,%3};"
        : "+f"(d[0]), "+f"(d[1]), "+f"(d[2]), "+f"(d[3])
        : "r"(a[0]), "r"(a[1]), "r"(a[2]), "r"(a[3]), "r"(b[0]), "r"(b[1]));
}

// ---------------------------------------------------------------------------
// prep: round f32 array to tf32 (RN)
// ---------------------------------------------------------------------------
__global__ void round_kernel(const float4* __restrict__ src, float4* __restrict__ dst, int n4)
{
    for (int i = blockIdx.x * blockDim.x + threadIdx.x; i < n4; i += gridDim.x * blockDim.x) {
        float4 v = src[i];
        v.x = tf32_rn(v.x); v.y = tf32_rn(v.y); v.z = tf32_rn(v.z); v.w = tf32_rn(v.w);
        dst[i] = v;
    }
}

// ---------------------------------------------------------------------------
// tf32 GEMM: C[m][n] = sum_k A[m][k]*B[n][k] + bias[n]
// A:[M][256], B:[N][256] row-major (tf32-valued f32). grid=(N/128, M/128).
// 256 thr, warps 2m x 4n (warp tile 64x32). 3-stage cp.async, k-chunk 32.
// smem stage: A 16KB + B 16KB, rows 128B, 16B-granule XOR swizzle.
// ---------------------------------------------------------------------------
#define STAGE_B 32768
__global__ void __launch_bounds__(256, 2)
gemm_mma_kernel(const float* __restrict__ A,
                const float* __restrict__ Bw,
                const float* __restrict__ bias,
                float* __restrict__ C, int N, int do_round)
{
    extern __shared__ char sm[];
    const uint32_t sb = smem_u32(sm);

    const int tid  = threadIdx.x;
    const int lane = tid & 31;
    const int wid  = tid >> 5;
    const int g    = lane >> 2;
    const int t4   = lane & 3;
    const int wm   = (wid & 1) * 64;
    const int wn   = (wid >> 1) * 32;
    const int m0   = blockIdx.y * 128;
    const int n0   = blockIdx.x * 128;

    const char* Ag = (const char*)(A  + (size_t)m0 * GK);
    const char* Bg = (const char*)(Bw + (size_t)n0 * GK);

    float acc[4][4][4];
#pragma unroll
    for (int i = 0; i < 4; i++)
#pragma unroll
        for (int j = 0; j < 4; j++)
#pragma unroll
            for (int c = 0; c < 4; c++) acc[i][j][c] = 0.f;

    // ldmatrix source rows (fixed per thread)
    int rowA[4];
#pragma unroll
    for (int mf = 0; mf < 4; mf++) rowA[mf] = wm + mf * 16 + (lane & 15);
    const int haA = lane >> 4;
    int rowB[2];
#pragma unroll
    for (int p = 0; p < 2; p++) rowB[p] = wn + p * 16 + (lane & 7) + ((lane & 16) ? 8 : 0);
    const int haB = (lane >> 3) & 1;

    auto load_stage = [&](int it, int s) {
        const uint32_t sa = sb + (uint32_t)s * STAGE_B;
#pragma unroll
        for (int i = 0; i < 4; i++) {
            const int idx = tid + i * 256;
            const int row = idx >> 3, c = idx & 7;
            const uint32_t off = (uint32_t)(row * 128 + ((c ^ (row & 7)) << 4));
            const size_t goff = (size_t)row * 1024 + it * 128 + c * 16;
            cp16(sa + off, Ag + goff);
            cp16(sa + 16384 + off, Bg + goff);
        }
        CP_COMMIT();
    };

    load_stage(0, 0);
    load_stage(1, 1);
    load_stage(2, 2);

#pragma unroll 1
    for (int it = 0; it < 8; it++) {
        if (it < 6) cp_wait<2>();
        else if (it == 6) cp_wait<1>();
        else cp_wait<0>();
        __syncthreads();

        const uint32_t sa = sb + (uint32_t)(it % 3) * STAGE_B;
#pragma unroll
        for (int s4 = 0; s4 < 4; s4++) {
            uint32_t a[4][4], b[4][2];
#pragma unroll
            for (int mf = 0; mf < 4; mf++) {
                const int r = rowA[mf];
                ldsm4(a[mf][0], a[mf][1], a[mf][2], a[mf][3],
                      sa + r * 128 + (((2 * s4 + haA) ^ (r & 7)) << 4));
            }
#pragma unroll
            for (int p = 0; p < 2; p++) {
                const int r = rowB[p];
                uint32_t r0, r1, r2, r3;
                ldsm4(r0, r1, r2, r3,
                      sa + 16384 + r * 128 + (((2 * s4 + haB) ^ (r & 7)) << 4));
                b[2 * p][0] = r0; b[2 * p][1] = r1;
                b[2 * p + 1][0] = r2; b[2 * p + 1][1] = r3;
            }
#pragma unroll
            for (int mf = 0; mf < 4; mf++)
#pragma unroll
                for (int nf = 0; nf < 4; nf++)
                    mma_tf32(acc[mf][nf], a[mf], b[nf]);
        }
        __syncthreads();
        if (it + 3 < 8) load_stage(it + 3, it % 3);
    }

    // epilogue
#pragma unroll
    for (int mf = 0; mf < 4; mf++) {
        const int r0 = m0 + wm + mf * 16 + g;
        const int r1 = r0 + 8;
#pragma unroll
        for (int nf = 0; nf < 4; nf++) {
            const int col = n0 + wn + nf * 8 + 2 * t4;
            const float2 bv = *(const float2*)&bias[col];
            float2 o0, o1;
            o0.x = acc[mf][nf][0] + bv.x;
            o0.y = acc[mf][nf][1] + bv.y;
            o1.x = acc[mf][nf][2] + bv.x;
            o1.y = acc[mf][nf][3] + bv.y;
            if (do_round) {
                o0.x = tf32_rn(o0.x); o0.y = tf32_rn(o0.y);
                o1.x = tf32_rn(o1.x); o1.y = tf32_rn(o1.y);
            }
            *(float2*)&C[(size_t)r0 * N + col] = o0;
            *(float2*)&C[(size_t)r1 * N + col] = o1;
        }
    }
}

// ---------------------------------------------------------------------------
// Window attention on tensor cores. Block = (window, head), 128 thr, 4 warps.
// qs/ks: 64 rows x 128B (swizzled). vT: 32 dim-rows x 256B. sc: 64 rows x 256B.
// ---------------------------------------------------------------------------
__global__ __launch_bounds__(128, 4)
void attn_kernel(const float* __restrict__ qkv,
                 const float* __restrict__ bias_table,
                 float* __restrict__ y)
{
    __shared__ float qs[WS * 32];
    __shared__ float ks[WS * 32];
    __shared__ float vT[HD * WS];
    __shared__ float sc[WS * WS];
    __shared__ float bt[225];

    const uint32_t qsb = smem_u32(qs);
    const uint32_t ksb = smem_u32(ks);
    const uint32_t vtb = smem_u32(vT);
    const uint32_t scb = smem_u32(sc);

    const int tid  = threadIdx.x;
    const int lane = tid & 31;
    const int wid  = tid >> 5;
    const int g    = lane >> 2;
    const int t4   = lane & 3;
    const int w    = blockIdx.x;
    const int hh   = blockIdx.y;
    const int bb   = w >> 10;
    const int widx = w & 1023;
    const int wr   = widx >> 5;
    const int wc   = widx & 31;

    if (tid < 128) {
        for (int i = tid; i < 225; i += 128) bt[i] = bias_table[i * HEADS + hh];
    }

    // ---- load q, k (swizzled 128B rows) ----
    for (int idx = tid; idx < 2 * WS * 8; idx += 128) {
        const int sel = idx >> 9;               // 0=q, 1=k
        const int rem = idx & 511;
        const int t   = rem >> 3;
        const int c   = rem & 7;
        const int trw = t >> 3, tcl = t & 7;
        const size_t tok = (size_t)bb * (IMG * IMG)
                         + (size_t)(wr * 8 + trw) * IMG + (wc * 8 + tcl);
        const float4 v4 = *(const float4*)&qkv[tok * QKV_DIM + sel * CDIM + hh * HD + c * 4];
        const uint32_t dst = (sel ? ksb : qsb) + t * 128 + ((c ^ (t & 7)) << 4);
        *(float4*)(uintptr_t)__cvta_shared_to_generic(dst) = v4;
    }
    // ---- load v transposed: vT[dim][key], 256B rows ----
    for (int idx = tid; idx < WS * 8; idx += 128) {
        const int t = idx >> 3;
        const int c = idx & 7;
        const int trw = t >> 3, tcl = t & 7;
        const size_t tok = (size_t)bb * (IMG * IMG)
                         + (size_t)(wr * 8 + trw) * IMG + (wc * 8 + tcl);
        const float4 v4 = *(const float4*)&qkv[tok * QKV_DIM + 2 * CDIM + hh * HD + c * 4];
        const float vv[4] = {v4.x, v4.y, v4.z, v4.w};
#pragma unroll
        for (int e = 0; e < 4; e++) {
            const int row = c * 4 + e;
            const uint32_t dst = vtb + row * 256 + (((t >> 2) ^ (row & 7)) << 4) + (t & 3) * 4;
            *(float*)(uintptr_t)__cvta_shared_to_generic(dst) = vv[e];
        }
    }
    __syncthreads();

    // ---- scores: warp handles 16 q-rows; 8 n-tiles x 4 k-steps ----
    {
        float s[8][4];
#pragma unroll
        for (int j = 0; j < 8; j++)
#pragma unroll
            for (int c = 0; c < 4; c++) s[j][c] = 0.f;

        const int rA = wid * 16 + (lane & 15);
        const int haA = lane >> 4;
        const int haB = (lane >> 3) & 1;

#pragma unroll
        for (int s4 = 0; s4 < 4; s4++) {
            uint32_t a[4];
            ldsm4(a[0], a[1], a[2], a[3],
                  qsb + rA * 128 + (((2 * s4 + haA) ^ (rA & 7)) << 4));
#pragma unroll
            for (int p = 0; p < 4; p++) {
                const int r = p * 16 + (lane & 7) + ((lane & 16) ? 8 : 0);
                uint32_t b0, b1, b2, b3;
                ldsm4(b0, b1, b2, b3,
                      ksb + r * 128 + (((2 * s4 + haB) ^ (r & 7)) << 4));
                uint32_t bA[2] = {b0, b1}, bB[2] = {b2, b3};
                mma_tf32(s[2 * p], a, bA);
                mma_tf32(s[2 * p + 1], a, bB);
            }
        }

        // epilogue: scale + bias, store to sc (swizzled), pre-softmax f32
        const float scale = 0.17677669529663687f;
        const int qr0 = wid * 16 + g;
        const int qr1 = qr0 + 8;
#pragma unroll
        for (int j = 0; j < 8; j++) {
            const int col = j * 8 + 2 * t4;
            const int ki = col >> 3, kj = col & 7;
            const int ki2 = (col + 1) >> 3, kj2 = (col + 1) & 7;
            {
                const int qi = qr0 >> 3, qj = qr0 & 7;
                float2 o;
                o.x = s[j][0] * scale + bt[(qi - ki + 7) * 15 + (qj - kj + 7)];
                o.y = s[j][1] * scale + bt[(qi - ki2 + 7) * 15 + (qj - kj2 + 7)];
                const int cgr = col >> 2;
                const uint32_t dst = scb + qr0 * 256 + ((cgr ^ (qr0 & 7)) << 4) + (t4 & 1) * 8;
                *(float2*)(uintptr_t)__cvta_shared_to_generic(dst) = o;
            }
            {
                const int qi = qr1 >> 3, qj = qr1 & 7;
                float2 o;
                o.x = s[j][2] * scale + bt[(qi - ki + 7) * 15 + (qj - kj + 7)];
                o.y = s[j][3] * scale + bt[(qi - ki2 + 7) * 15 + (qj - kj2 + 7)];
                const int cgr = col >> 2;
                const uint32_t dst = scb + qr1 * 256 + ((cgr ^ (qr1 & 7)) << 4) + (t4 & 1) * 8;
                *(float2*)(uintptr_t)__cvta_shared_to_generic(dst) = o;
            }
        }
    }
    __syncthreads();

    // ---- softmax: 2 threads per row; probs rounded to tf32 ----
    {
        const int row  = tid >> 1;
        const int half = tid & 1;
        float4 vv[8];
        float m = -1e30f;
#pragma unroll
        for (int j = 0; j < 8; j++) {
            const int c = half * 8 + j;
            const uint32_t a = scb + row * 256 + ((c ^ (row & 7)) << 4);
            vv[j] = *(const float4*)(uintptr_t)__cvta_shared_to_generic(a);
            m = fmaxf(m, fmaxf(fmaxf(vv[j].x, vv[j].y), fmaxf(vv[j].z, vv[j].w)));
        }
        const float mo = __shfl_xor_sync(0xffffffffu, m, 1);
        const float M = fmaxf(m, mo);
        float ssum = 0.f;
#pragma unroll
        for (int j = 0; j < 8; j++) {
            vv[j].x = __expf(vv[j].x - M); vv[j].y = __expf(vv[j].y - M);
            vv[j].z = __expf(vv[j].z - M); vv[j].w = __expf(vv[j].w - M);
            ssum += vv[j].x + vv[j].y + vv[j].z + vv[j].w;
        }
        const float so = __shfl_xor_sync(0xffffffffu, ssum, 1);
        const float inv = 1.f / (ssum + so);
#pragma unroll
        for (int j = 0; j < 8; j++) {
            const int c = half * 8 + j;
            float4 o;
            o.x = tf32_rn(vv[j].x * inv); o.y = tf32_rn(vv[j].y * inv);
            o.z = tf32_rn(vv[j].z * inv); o.w = tf32_rn(vv[j].w * inv);
            const uint32_t a = scb + row * 256 + ((c ^ (row & 7)) << 4);
            *(float4*)(uintptr_t)__cvta_shared_to_generic(a) = o;
        }
    }
    __syncthreads();

    // ---- AV: warp 16 q-rows; 4 n-tiles (32 dims) x 8 k-steps (64 keys) ----
    {
        float o[4][4];
#pragma unroll
        for (int j = 0; j < 4; j++)
#pragma unroll
            for (int c = 0; c < 4; c++) o[j][c] = 0.f;

        const int rA = wid * 16 + (lane & 15);
        const int haA = lane >> 4;
        const int haB = (lane >> 3) & 1;

#pragma unroll
        for (int s8 = 0; s8 < 8; s8++) {
            uint32_t a[4];
            const int cA = 2 * s8 + haA;
            ldsm4(a[0], a[1], a[2], a[3],
                  scb + rA * 256 + ((cA ^ (rA & 7)) << 4));
#pragma unroll
            for (int p = 0; p < 2; p++) {
                const int r = p * 16 + (lane & 7) + ((lane & 16) ? 8 : 0);
                const int cB = 2 * s8 + haB;
                uint32_t b0, b1, b2, b3;
                ldsm4(b0, b1, b2, b3,
                      vtb + r * 256 + ((cB ^ (r & 7)) << 4));
                uint32_t bA[2] = {b0, b1}, bB[2] = {b2, b3};
                mma_tf32(o[2 * p], a, bA);
                mma_tf32(o[2 * p + 1], a, bB);
            }
        }

        // write y (rounded to tf32 for the next GEMM)
#pragma unroll
        for (int rr = 0; rr < 2; rr++) {
            const int qr = wid * 16 + g + rr * 8;
            const int trw = qr >> 3, tcl = qr & 7;
            const size_t tok = (size_t)bb * (IMG * IMG)
                             + (size_t)(wr * 8 + trw) * IMG + (wc * 8 + tcl);
            float* dst = &y[tok * CDIM + hh * HD];
#pragma unroll
            for (int j = 0; j < 4; j++) {
                const int col = j * 8 + 2 * t4;
                float2 ov;
                ov.x = tf32_rn(o[j][rr * 2 + 0]);
                ov.y = tf32_rn(o[j][rr * 2 + 1]);
                *(float2*)&dst[col] = ov;
            }
        }
    }
}

// ---------------------------------------------------------------------------
extern "C" void kernel_launch(void* const* d_in, const int* in_sizes, int n_in,
                              void* d_out, int out_size)
{
    (void)in_sizes; (void)n_in; (void)out_size;
    const float* x          = (const float*)d_in[0];
    const float* wqkv_w     = (const float*)d_in[3];
    const float* wqkv_b     = (const float*)d_in[4];
    const float* wp_w       = (const float*)d_in[5];
    const float* wp_b       = (const float*)d_in[6];
    const float* bias_table = (const float*)d_in[7];
    float* out = (float*)d_out;

    float *xr, *wqr, *wpr, *qkv_ptr, *y_ptr;
    cudaGetSymbolAddress((void**)&xr, g_x);
    cudaGetSymbolAddress((void**)&wqr, g_wq);
    cudaGetSymbolAddress((void**)&wpr, g_wp);
    cudaGetSymbolAddress((void**)&qkv_ptr, g_qkv);
    cudaGetSymbolAddress((void**)&y_ptr, g_y);

    static bool attr_set = false;
    if (!attr_set) {
        cudaFuncSetAttribute(gemm_mma_kernel,
                             cudaFuncAttributeMaxDynamicSharedMemorySize, 3 * STAGE_B);
        attr_set = true;
    }

    // 0) round inputs to tf32 (RN)
    round_kernel<<<4096, 256>>>((const float4*)x, (float4*)xr, NTOK * CDIM / 4);
    round_kernel<<<256, 256>>>((const float4*)wqkv_w, (float4*)wqr, QKV_DIM * CDIM / 4);
    round_kernel<<<128, 256>>>((const float4*)wp_w, (float4*)wpr, CDIM * CDIM / 4);

    // 1) QKV projection (epilogue rounds to tf32 for attention)
    gemm_mma_kernel<<<dim3(QKV_DIM / 128, NTOK / 128), 256, 3 * STAGE_B>>>(
        xr, wqr, wqkv_b, qkv_ptr, QKV_DIM, 1);

    // 2) windowed attention (tensor cores)
    attn_kernel<<<dim3(NWIN, HEADS), 128>>>(qkv_ptr, bias_table, y_ptr);

    // 3) output projection (final output, no rounding)
    gemm_mma_kernel<<<dim3(CDIM / 128, NTOK / 128), 256, 3 * STAGE_B>>>(
        y_ptr, wpr, wp_b, out, CDIM, 0);
}